// round 2
// baseline (speedup 1.0000x reference)
#include <cuda_runtime.h>
#include <cstdint>

// Problem constants (fixed by the reference: B=4, T=2048, S=4, D=1024)
#define BT      8192        // B*T
#define SDIM    4
#define DDIM    1024
#define DVEC    256         // D/4 float4 per row
#define SINKHORN_ITERS 20
#define EPS_SK  1e-8f

// Device-side scratch (allocation-free rule: use __device__ globals)
__device__ float d_M[16];       // M[sp*4+s] = (sp==s) + alpha_res * P[sp][s]
__device__ float d_g[4];        // alpha_pos * H_pos[s]
__device__ float d_biasC[SDIM * DDIM];  // bias_res + bias_pos, [s][d]

// ---------------------------------------------------------------------------
// Prep: Sinkhorn on the 4x4 matrix + fold scalars/biases. One block.
// ---------------------------------------------------------------------------
__global__ void prep_kernel(const float* __restrict__ H_res,
                            const float* __restrict__ H_pos,
                            const float* __restrict__ alpha_res,
                            const float* __restrict__ alpha_pos,
                            const float* __restrict__ bias_res,
                            const float* __restrict__ bias_pos)
{
    if (threadIdx.x == 0) {
        float P[4][4];
        // P = exp(H - rowmax)
        for (int r = 0; r < 4; r++) {
            float m = H_res[r * 4 + 0];
            for (int c = 1; c < 4; c++) m = fmaxf(m, H_res[r * 4 + c]);
            for (int c = 0; c < 4; c++) P[r][c] = __expf(H_res[r * 4 + c] - m);
        }
        // Alternating row/column normalization
        for (int it = 0; it < SINKHORN_ITERS; it++) {
            for (int r = 0; r < 4; r++) {
                float s = P[r][0] + P[r][1] + P[r][2] + P[r][3] + EPS_SK;
                float inv = 1.0f / s;
                for (int c = 0; c < 4; c++) P[r][c] *= inv;
            }
            for (int c = 0; c < 4; c++) {
                float s = P[0][c] + P[1][c] + P[2][c] + P[3][c] + EPS_SK;
                float inv = 1.0f / s;
                for (int r = 0; r < 4; r++) P[r][c] *= inv;
            }
        }
        float ar = *alpha_res;
        float ap = *alpha_pos;
        for (int sp = 0; sp < 4; sp++)
            for (int s = 0; s < 4; s++)
                d_M[sp * 4 + s] = (sp == s ? 1.0f : 0.0f) + ar * P[sp][s];
        for (int s = 0; s < 4; s++)
            d_g[s] = ap * H_pos[s];
    }
    // Combined bias (16 KB) — all threads
    for (int i = threadIdx.x; i < SDIM * DDIM; i += blockDim.x)
        d_biasC[i] = bias_res[i] + bias_pos[i];
}

// ---------------------------------------------------------------------------
// Main fused kernel: each thread = one (bt, dvec) column across all 4 streams.
//   out[bt,s,dv] = sum_sp M[sp][s]*x[bt,sp,dv] + g[s]*lo[bt,dv] + biasC[s,dv]
// ---------------------------------------------------------------------------
__global__ __launch_bounds__(256)
void mhc_residual_kernel(const float4* __restrict__ x,
                         const float4* __restrict__ lo,
                         float4* __restrict__ out)
{
    __shared__ float sM[16];
    __shared__ float sg[4];
    if (threadIdx.x < 16) sM[threadIdx.x] = d_M[threadIdx.x];
    if (threadIdx.x < 4)  sg[threadIdx.x] = d_g[threadIdx.x];
    __syncthreads();

    unsigned idx = blockIdx.x * blockDim.x + threadIdx.x;  // 0 .. BT*DVEC-1
    unsigned dvec = idx & (DVEC - 1);
    unsigned bt   = idx >> 8;  // log2(DVEC) = 8

    const float4* xr = x + (size_t)bt * (SDIM * DVEC) + dvec;
    float4 x0 = __ldg(xr + 0 * DVEC);
    float4 x1 = __ldg(xr + 1 * DVEC);
    float4 x2 = __ldg(xr + 2 * DVEC);
    float4 x3 = __ldg(xr + 3 * DVEC);
    float4 l  = __ldg(lo + (size_t)bt * DVEC + dvec);

    const float4* bC = reinterpret_cast<const float4*>(d_biasC) + dvec;
    float4* outr = out + (size_t)bt * (SDIM * DVEC) + dvec;

#pragma unroll
    for (int s = 0; s < 4; s++) {
        float m0 = sM[0 * 4 + s];
        float m1 = sM[1 * 4 + s];
        float m2 = sM[2 * 4 + s];
        float m3 = sM[3 * 4 + s];
        float g  = sg[s];
        float4 b = __ldg(bC + s * DVEC);
        float4 o;
        o.x = fmaf(m0, x0.x, fmaf(m1, x1.x, fmaf(m2, x2.x, fmaf(m3, x3.x, fmaf(g, l.x, b.x)))));
        o.y = fmaf(m0, x0.y, fmaf(m1, x1.y, fmaf(m2, x2.y, fmaf(m3, x3.y, fmaf(g, l.y, b.y)))));
        o.z = fmaf(m0, x0.z, fmaf(m1, x1.z, fmaf(m2, x2.z, fmaf(m3, x3.z, fmaf(g, l.z, b.z)))));
        o.w = fmaf(m0, x0.w, fmaf(m1, x1.w, fmaf(m2, x2.w, fmaf(m3, x3.w, fmaf(g, l.w, b.w)))));
        outr[s * DVEC] = o;
    }
}

// ---------------------------------------------------------------------------
// Launch. Inputs per metadata order:
//   0: x (B,T,S,D) f32   1: layer_output (B,T,D) f32   2: H_res (S,S) f32
//   3: H_pos (S,1) f32   4: alpha_res f32 scalar        5: alpha_pos f32 scalar
//   6: bias_res (S,D)    7: bias_pos (S,D)
// ---------------------------------------------------------------------------
extern "C" void kernel_launch(void* const* d_in, const int* in_sizes, int n_in,
                              void* d_out, int out_size)
{
    const float* x         = (const float*)d_in[0];
    const float* lo        = (const float*)d_in[1];
    const float* H_res     = (const float*)d_in[2];
    const float* H_pos     = (const float*)d_in[3];
    const float* alpha_res = (const float*)d_in[4];
    const float* alpha_pos = (const float*)d_in[5];
    const float* bias_res  = (const float*)d_in[6];
    const float* bias_pos  = (const float*)d_in[7];
    float* out             = (float*)d_out;

    prep_kernel<<<1, 256>>>(H_res, H_pos, alpha_res, alpha_pos, bias_res, bias_pos);

    const unsigned total = BT * DVEC;          // 2,097,152 threads
    const unsigned threads = 256;
    mhc_residual_kernel<<<total / threads, threads>>>(
        (const float4*)x, (const float4*)lo, (float4*)out);
}

// round 3
// speedup vs baseline: 1.1021x; 1.1021x over previous
#include <cuda_runtime.h>
#include <cstdint>

// Problem constants (fixed by the reference: B=4, T=2048, S=4, D=1024)
#define BT      8192        // B*T
#define SDIM    4
#define DDIM    1024
#define DVEC    256         // D/4 float4 per row
#define SINKHORN_ITERS 20
#define EPS_SK  1e-8f

// Device-side scratch (allocation-free rule: use __device__ globals)
__device__ float d_M[16];       // M[sp*4+s] = (sp==s) + alpha_res * P[sp][s]
__device__ float d_g[4];        // alpha_pos * H_pos[s]

// ---------------------------------------------------------------------------
// Prep: Sinkhorn on the 4x4 matrix only. One warp, ~80 bytes of output.
// ---------------------------------------------------------------------------
__global__ void prep_kernel(const float* __restrict__ H_res,
                            const float* __restrict__ H_pos,
                            const float* __restrict__ alpha_res,
                            const float* __restrict__ alpha_pos)
{
    if (threadIdx.x != 0) return;
    float P[4][4];
    // P = exp(H - rowmax)
    for (int r = 0; r < 4; r++) {
        float m = H_res[r * 4 + 0];
        for (int c = 1; c < 4; c++) m = fmaxf(m, H_res[r * 4 + c]);
        for (int c = 0; c < 4; c++) P[r][c] = __expf(H_res[r * 4 + c] - m);
    }
    // Alternating row/column normalization
    for (int it = 0; it < SINKHORN_ITERS; it++) {
        for (int r = 0; r < 4; r++) {
            float s = P[r][0] + P[r][1] + P[r][2] + P[r][3] + EPS_SK;
            float inv = 1.0f / s;
            for (int c = 0; c < 4; c++) P[r][c] *= inv;
        }
        for (int c = 0; c < 4; c++) {
            float s = P[0][c] + P[1][c] + P[2][c] + P[3][c] + EPS_SK;
            float inv = 1.0f / s;
            for (int r = 0; r < 4; r++) P[r][c] *= inv;
        }
    }
    float ar = *alpha_res;
    float ap = *alpha_pos;
    for (int sp = 0; sp < 4; sp++)
        for (int s = 0; s < 4; s++)
            d_M[sp * 4 + s] = (sp == s ? 1.0f : 0.0f) + ar * P[sp][s];
    for (int s = 0; s < 4; s++)
        d_g[s] = ap * H_pos[s];
}

// ---------------------------------------------------------------------------
// Main fused kernel: each thread = one (bt, dvec) column across all 4 streams.
//   out[bt,s,dv] = sum_sp M[sp][s]*x[bt,sp,dv] + g[s]*lo[bt,dv]
//                  + bias_res[s,dv] + bias_pos[s,dv]
// Bias tensors (32 KB total) are L2-resident and combined inline.
// ---------------------------------------------------------------------------
__global__ __launch_bounds__(256)
void mhc_residual_kernel(const float4* __restrict__ x,
                         const float4* __restrict__ lo,
                         const float4* __restrict__ br,
                         const float4* __restrict__ bp,
                         float4* __restrict__ out)
{
    __shared__ float sM[16];
    __shared__ float sg[4];
    if (threadIdx.x < 16) sM[threadIdx.x] = d_M[threadIdx.x];
    if (threadIdx.x < 4)  sg[threadIdx.x] = d_g[threadIdx.x];

    unsigned idx = blockIdx.x * blockDim.x + threadIdx.x;  // 0 .. BT*DVEC-1
    unsigned dvec = idx & (DVEC - 1);
    unsigned bt   = idx >> 8;  // log2(DVEC) = 8

    // Front-batch the DRAM-bound loads (streaming: no reuse -> evict-first)
    const float4* xr = x + (size_t)bt * (SDIM * DVEC) + dvec;
    float4 x0 = __ldcs(xr + 0 * DVEC);
    float4 x1 = __ldcs(xr + 1 * DVEC);
    float4 x2 = __ldcs(xr + 2 * DVEC);
    float4 x3 = __ldcs(xr + 3 * DVEC);
    float4 l  = __ldcs(lo + (size_t)bt * DVEC + dvec);

    __syncthreads();

    float4* outr = out + (size_t)bt * (SDIM * DVEC) + dvec;

#pragma unroll
    for (int s = 0; s < 4; s++) {
        float m0 = sM[0 * 4 + s];
        float m1 = sM[1 * 4 + s];
        float m2 = sM[2 * 4 + s];
        float m3 = sM[3 * 4 + s];
        float g  = sg[s];
        // Bias: L2-resident broadcast loads, combined inline
        float4 a = __ldg(br + s * DVEC + dvec);
        float4 c = __ldg(bp + s * DVEC + dvec);
        float4 b;
        b.x = a.x + c.x; b.y = a.y + c.y; b.z = a.z + c.z; b.w = a.w + c.w;
        float4 o;
        o.x = fmaf(m0, x0.x, fmaf(m1, x1.x, fmaf(m2, x2.x, fmaf(m3, x3.x, fmaf(g, l.x, b.x)))));
        o.y = fmaf(m0, x0.y, fmaf(m1, x1.y, fmaf(m2, x2.y, fmaf(m3, x3.y, fmaf(g, l.y, b.y)))));
        o.z = fmaf(m0, x0.z, fmaf(m1, x1.z, fmaf(m2, x2.z, fmaf(m3, x3.z, fmaf(g, l.z, b.z)))));
        o.w = fmaf(m0, x0.w, fmaf(m1, x1.w, fmaf(m2, x2.w, fmaf(m3, x3.w, fmaf(g, l.w, b.w)))));
        __stcs(outr + s * DVEC, o);
    }
}

// ---------------------------------------------------------------------------
// Launch. Inputs per metadata order:
//   0: x (B,T,S,D) f32   1: layer_output (B,T,D) f32   2: H_res (S,S) f32
//   3: H_pos (S,1) f32   4: alpha_res f32 scalar        5: alpha_pos f32 scalar
//   6: bias_res (S,D)    7: bias_pos (S,D)
// ---------------------------------------------------------------------------
extern "C" void kernel_launch(void* const* d_in, const int* in_sizes, int n_in,
                              void* d_out, int out_size)
{
    const float* x         = (const float*)d_in[0];
    const float* lo        = (const float*)d_in[1];
    const float* H_res     = (const float*)d_in[2];
    const float* H_pos     = (const float*)d_in[3];
    const float* alpha_res = (const float*)d_in[4];
    const float* alpha_pos = (const float*)d_in[5];
    const float* bias_res  = (const float*)d_in[6];
    const float* bias_pos  = (const float*)d_in[7];
    float* out             = (float*)d_out;

    prep_kernel<<<1, 32>>>(H_res, H_pos, alpha_res, alpha_pos);

    const unsigned total = BT * DVEC;          // 2,097,152 threads
    const unsigned threads = 256;
    mhc_residual_kernel<<<total / threads, threads>>>(
        (const float4*)x, (const float4*)lo,
        (const float4*)bias_res, (const float4*)bias_pos, (float4*)out);
}